// round 6
// baseline (speedup 1.0000x reference)
#include <cuda_runtime.h>

// Problem shape (fixed by dataset): D=1024, P=256, R=64, K=1024
#define D_DIRS 1024
#define P_PTS  256
#define R_RANK 64
#define K_SUB  1024

#define TAIL_BLOCKS 64

// Scratch (allocation-free rule: __device__ globals; zero-initialized at load)
__device__ float g_asum[D_DIRS * R_RANK];   // sum over p of attenuation
__device__ float g_bsum[D_DIRS * R_RANK];   // sum over p of radiation
__device__ float g_M[R_RANK * R_RANK];      // M accumulator (zeroed at tail end)
__device__ unsigned g_c1, g_c2, g_c3;       // barrier counters (reset each run)

// ---------------------------------------------------------------------------
// Kernel 1: reduce over P. One block per (tensor, d) — 2048 short-lived,
// barrier-light blocks; proven ~23.8us @ 72% DRAM. Do not restructure.
// ---------------------------------------------------------------------------
__global__ __launch_bounds__(256) void reduce_p_kernel(
    const float* __restrict__ atten, const float* __restrict__ rad)
{
    const int b = blockIdx.x;
    const bool is_b = (b >= D_DIRS);
    const int d = b & (D_DIRS - 1);
    const float* __restrict__ src = is_b ? rad : atten;
    float* __restrict__ dst = is_b ? g_bsum : g_asum;

    const float4* __restrict__ in =
        reinterpret_cast<const float4*>(src) + (size_t)d * (P_PTS * R_RANK / 4);

    const int t = threadIdx.x;

    float4 acc = make_float4(0.f, 0.f, 0.f, 0.f);
    #pragma unroll
    for (int i = 0; i < 16; i++) {
        float4 v = __ldcs(&in[i * 256 + t]);
        acc.x += v.x; acc.y += v.y; acc.z += v.z; acc.w += v.w;
    }

    __shared__ float4 s[256];
    s[t] = acc;
    __syncthreads();

    if (t < 16) {
        float4 sum = s[t];
        #pragma unroll
        for (int j = 1; j < 16; j++) {
            float4 v = s[j * 16 + t];
            sum.x += v.x; sum.y += v.y; sum.z += v.z; sum.w += v.w;
        }
        reinterpret_cast<float4*>(dst + d * R_RANK)[t] = sum;
    }
}

// acquire load for barrier polling — plain L2 read, no RMW serialization
__device__ __forceinline__ unsigned ld_acquire(const unsigned* p)
{
    unsigned v;
    asm volatile("ld.acquire.gpu.global.u32 %0, [%1];" : "=r"(v) : "l"(p));
    return v;
}

// grid-wide spin barrier for 64 co-resident blocks.
// Arrive: one atomicAdd. Poll: acquire LOADS (cheap broadcast at L2).
__device__ __forceinline__ void grid_barrier(unsigned* ctr)
{
    __syncthreads();
    if (threadIdx.x == 0) {
        __threadfence();                       // release prior writes
        atomicAdd(ctr, 1u);
        while (ld_acquire(ctr) < (unsigned)TAIL_BLOCKS) { }
    }
    __syncthreads();
}

// ---------------------------------------------------------------------------
// Kernel 2 (tail): partial-M + atomic accumulate (depth 64) -> barrier ->
// quadform -> barrier -> self-zero g_M + reset counters.
// grid = 64 blocks x 256 threads (all co-resident).
// ---------------------------------------------------------------------------
__global__ __launch_bounds__(256) void tail_kernel(
    const float* __restrict__ F, float* __restrict__ out)
{
    __shared__ __align__(16) float pool[5120];   // 20 KB, reused across phases
    const int t = threadIdx.x;
    const int b = blockIdx.x;

    // ============ Phase 1: partial M over 16 d's -> atomicAdd into g_M ====
    {
        float* sA = pool;          // [16][64]
        float* sB = pool + 1024;   // [16][64]
        const int dbase = b * 16;

        reinterpret_cast<float4*>(sA)[t] =
            reinterpret_cast<const float4*>(g_asum + dbase * R_RANK)[t];
        reinterpret_cast<float4*>(sB)[t] =
            reinterpret_cast<const float4*>(g_bsum + dbase * R_RANK)[t];
        __syncthreads();

        const int r1  = t >> 2;
        const int r2b = (t & 3) * 16;

        float macc[16];
        #pragma unroll
        for (int j = 0; j < 16; j++) macc[j] = 0.f;

        #pragma unroll
        for (int i = 0; i < 16; i++) {
            const float a = sA[i * R_RANK + r1];
            #pragma unroll
            for (int j = 0; j < 16; j++)
                macc[j] += a * sB[i * R_RANK + r2b + j];
        }

        // depth-64 contention per address: cheap (proven in round 3)
        #pragma unroll
        for (int j = 0; j < 16; j++)
            atomicAdd(&g_M[r1 * R_RANK + r2b + j], macc[j]);
    }

    grid_barrier(&g_c1);   // all atomics into g_M complete

    // ============ Phase 2: quadform for k in [16b, 16b+16) ================
    {
        float* Msh = pool;          // [64][64] = 16 KB
        float* fsh = pool + 4096;   // [16][64] = 4 KB

        #pragma unroll
        for (int i = 0; i < 4; i++)
            reinterpret_cast<float4*>(Msh)[i * 256 + t] =
                reinterpret_cast<const float4*>(g_M)[i * 256 + t];

        reinterpret_cast<float4*>(fsh)[t] =
            reinterpret_cast<const float4*>(F + (size_t)b * 16 * R_RANK)[t];
        __syncthreads();

        const int klocal = t >> 4;   // 0..15
        const int l16    = t & 15;   // owns float4 at r2 = 4*l16
        const float* fk  = fsh + klocal * R_RANK;
        const float4* M4 = reinterpret_cast<const float4*>(Msh);

        float4 acc = make_float4(0.f, 0.f, 0.f, 0.f);
        #pragma unroll
        for (int r1 = 0; r1 < R_RANK; r1++) {
            const float fv = fk[r1];
            const float4 m = M4[r1 * 16 + l16];
            acc.x += fv * m.x; acc.y += fv * m.y;
            acc.z += fv * m.z; acc.w += fv * m.w;
        }
        const float4 fq = reinterpret_cast<const float4*>(fk)[l16];
        float val = acc.x * fq.x + acc.y * fq.y + acc.z * fq.z + acc.w * fq.w;

        #pragma unroll
        for (int off = 8; off > 0; off >>= 1)
            val += __shfl_xor_sync(0xffffffffu, val, off);

        if (l16 == 0)
            out[b * 16 + klocal] = val * (1.0f / (float)D_DIRS);
    }

    grid_barrier(&g_c2);   // all blocks have staged g_M into smem

    // ============ Phase 3: zero g_M row b for the next replay =============
    if (t < 16)
        reinterpret_cast<float4*>(g_M + b * R_RANK)[t] =
            make_float4(0.f, 0.f, 0.f, 0.f);

    // last block to finish resets the barrier counters
    __syncthreads();
    if (t == 0) {
        __threadfence();
        unsigned old = atomicAdd(&g_c3, 1u);
        if (old == (unsigned)(TAIL_BLOCKS - 1)) {
            g_c1 = 0u; g_c2 = 0u; g_c3 = 0u;
            __threadfence();
        }
    }
}

extern "C" void kernel_launch(void* const* d_in, const int* in_sizes, int n_in,
                              void* d_out, int out_size)
{
    const float* atten = (const float*)d_in[0];   // [D,P,R] fp32
    const float* rad   = (const float*)d_in[1];   // [D,P,R] fp32
    const float* F     = (const float*)d_in[2];   // [K,R]   fp32
    float* out = (float*)d_out;                   // [K]     fp32

    (void)in_sizes; (void)n_in; (void)out_size;

    reduce_p_kernel<<<2 * D_DIRS, 256>>>(atten, rad);
    tail_kernel<<<TAIL_BLOCKS, 256>>>(F, out);
}

// round 7
// speedup vs baseline: 1.0007x; 1.0007x over previous
#include <cuda_runtime.h>

// Problem shape (fixed by dataset): D=1024, P=256, R=64, K=1024
#define D_DIRS 1024
#define P_PTS  256
#define R_RANK 64
#define K_SUB  1024

#define PREFETCH_BLOCKS 16   // extra blocks in kernel 1 that warm L2 with F

// Scratch (allocation-free rule: __device__ globals)
__device__ float g_asum[D_DIRS * R_RANK];   // sum over p of attenuation
__device__ float g_bsum[D_DIRS * R_RANK];   // sum over p of radiation
__device__ float g_M[R_RANK * R_RANK];      // M[r1][r2] (plain stores, no memset needed)
__device__ float g_sink[PREFETCH_BLOCKS];   // keeps F-prefetch alive

// ---------------------------------------------------------------------------
// Kernel 1: reduce over P. One block per (tensor, d) — 2048 short-lived,
// barrier-light blocks; proven ~23.8us @ 72% DRAM. 16 extra blocks prefetch
// F (256 KB) into L2 so the quadform kernel hits L2 instead of DRAM.
// ---------------------------------------------------------------------------
__global__ __launch_bounds__(256) void reduce_p_kernel(
    const float* __restrict__ atten, const float* __restrict__ rad,
    const float* __restrict__ F)
{
    const int b = blockIdx.x;
    const int t = threadIdx.x;

    if (b >= 2 * D_DIRS) {
        // ---- F prefetch: 16 blocks x 16 KB = 256 KB into L2 ----
        const int pb = b - 2 * D_DIRS;
        const float4* __restrict__ f4 =
            reinterpret_cast<const float4*>(F) + (size_t)pb * 1024;
        float4 acc = make_float4(0.f, 0.f, 0.f, 0.f);
        #pragma unroll
        for (int i = 0; i < 4; i++) {
            float4 v = f4[i * 256 + t];   // default caching -> lands in L2
            acc.x += v.x; acc.y += v.y; acc.z += v.z; acc.w += v.w;
        }
        // keep it alive (never read; negligible traffic)
        if (t == 0) g_sink[pb] = acc.x + acc.y + acc.z + acc.w;
        return;
    }

    const bool is_b = (b >= D_DIRS);
    const int d = b & (D_DIRS - 1);
    const float* __restrict__ src = is_b ? rad : atten;
    float* __restrict__ dst = is_b ? g_bsum : g_asum;

    const float4* __restrict__ in =
        reinterpret_cast<const float4*>(src) + (size_t)d * (P_PTS * R_RANK / 4);

    float4 acc = make_float4(0.f, 0.f, 0.f, 0.f);
    #pragma unroll
    for (int i = 0; i < 16; i++) {
        float4 v = __ldcs(&in[i * 256 + t]);
        acc.x += v.x; acc.y += v.y; acc.z += v.z; acc.w += v.w;
    }

    __shared__ float4 s[256];
    s[t] = acc;
    __syncthreads();

    if (t < 16) {
        float4 sum = s[t];
        #pragma unroll
        for (int j = 1; j < 16; j++) {
            float4 v = s[j * 16 + t];
            sum.x += v.x; sum.y += v.y; sum.z += v.z; sum.w += v.w;
        }
        reinterpret_cast<float4*>(dst + d * R_RANK)[t] = sum;
    }
}

// ---------------------------------------------------------------------------
// Kernel 2: M row r1 = sum_d asum[d,r1] * bsum[d,:].
// 64 blocks (one per r1) x 256 threads. asum column staged in smem;
// bsum streamed from L2 (coalesced per-d rows). Plain stores -> no atomics,
// no memset, no inter-block dependency.
// ---------------------------------------------------------------------------
__global__ __launch_bounds__(256) void make_m_kernel()
{
    const int r1 = blockIdx.x;
    const int t  = threadIdx.x;

    __shared__ float sCol[D_DIRS];    // asum[:, r1]
    __shared__ float red[256];

    #pragma unroll
    for (int i = 0; i < 4; i++)
        sCol[i * 256 + t] = g_asum[(size_t)(i * 256 + t) * R_RANK + r1];
    __syncthreads();

    const int r2 = t & 63;
    const int g  = t >> 6;            // 4 d-phases of 256

    float acc = 0.f;
    const float* __restrict__ bp = g_bsum + (size_t)g * 256 * R_RANK + r2;
    #pragma unroll 8
    for (int i = 0; i < 256; i++)
        acc += sCol[g * 256 + i] * bp[i * R_RANK];

    red[t] = acc;
    __syncthreads();
    if (t < 64)
        g_M[r1 * R_RANK + t] = red[t] + red[64 + t] + red[128 + t] + red[192 + t];
}

// ---------------------------------------------------------------------------
// Kernel 3: csi[k] = (1/D) * f_k^T M f_k.
// grid=128 x 256 threads: one warp per k (8 k's per block), lane owns an r2
// float2. F loaded FIRST (L2-hot from prefetch), then M; both staged in smem.
// ---------------------------------------------------------------------------
__global__ __launch_bounds__(256) void quadform_kernel(
    const float* __restrict__ F, float* __restrict__ out)
{
    __shared__ float Msh[R_RANK * R_RANK];   // 16 KB
    __shared__ float fsh[8][R_RANK];         // 2 KB

    const int t    = threadIdx.x;
    const int w    = t >> 5;      // warp = local k
    const int lane = t & 31;
    const int k    = blockIdx.x * 8 + w;

    // F first (should be L2-resident from kernel-1 prefetch)
    if (t < 128)
        reinterpret_cast<float4*>(&fsh[0][0])[t] =
            reinterpret_cast<const float4*>(F + (size_t)blockIdx.x * 8 * R_RANK)[t];

    #pragma unroll
    for (int i = 0; i < 4; i++)
        reinterpret_cast<float4*>(Msh)[i * 256 + t] =
            reinterpret_cast<const float4*>(g_M)[i * 256 + t];
    __syncthreads();

    float2 acc = make_float2(0.f, 0.f);
    const float2* __restrict__ M2 = reinterpret_cast<const float2*>(Msh);
    #pragma unroll
    for (int r1 = 0; r1 < R_RANK; r1++) {
        const float fv = fsh[w][r1];          // warp-uniform broadcast
        const float2 m = M2[r1 * 32 + lane];
        acc.x += fv * m.x;
        acc.y += fv * m.y;
    }
    float val = acc.x * fsh[w][2 * lane] + acc.y * fsh[w][2 * lane + 1];

    #pragma unroll
    for (int off = 16; off > 0; off >>= 1)
        val += __shfl_xor_sync(0xffffffffu, val, off);

    if (lane == 0)
        out[k] = val * (1.0f / (float)D_DIRS);
}

extern "C" void kernel_launch(void* const* d_in, const int* in_sizes, int n_in,
                              void* d_out, int out_size)
{
    const float* atten = (const float*)d_in[0];   // [D,P,R] fp32
    const float* rad   = (const float*)d_in[1];   // [D,P,R] fp32
    const float* F     = (const float*)d_in[2];   // [K,R]   fp32
    float* out = (float*)d_out;                   // [K]     fp32

    (void)in_sizes; (void)n_in; (void)out_size;

    reduce_p_kernel<<<2 * D_DIRS + PREFETCH_BLOCKS, 256>>>(atten, rad, F);
    make_m_kernel<<<R_RANK, 256>>>();
    quadform_kernel<<<K_SUB / 8, 256>>>(F, out);
}

// round 8
// speedup vs baseline: 1.1958x; 1.1949x over previous
#include <cuda_runtime.h>

// Problem shape (fixed by dataset): D=1024, P=256, R=64, K=1024
#define D_DIRS 1024
#define P_PTS  256
#define R_RANK 64
#define K_SUB  1024

#define PREFETCH_BLOCKS 16   // extra blocks in kernel 1 that warm L2 with F
#define NPART 128            // partial-M blocks (8 d's each)

// Scratch (allocation-free rule: __device__ globals)
__device__ float g_asum[D_DIRS * R_RANK];          // sum over p of attenuation
__device__ float g_bsum[D_DIRS * R_RANK];          // sum over p of radiation
__device__ float g_part[NPART * R_RANK * R_RANK];  // per-block partial M (2 MB, rewritten)
__device__ float g_sink[PREFETCH_BLOCKS];          // keeps F-prefetch alive

// ---------------------------------------------------------------------------
// Kernel 1: reduce over P. One block per (tensor, d) — 2048 short-lived,
// barrier-light blocks; proven ~24us @ 72% DRAM. 16 extra blocks prefetch
// F (256 KB) into L2 so the tail hits L2 instead of DRAM.
// ---------------------------------------------------------------------------
__global__ __launch_bounds__(256) void reduce_p_kernel(
    const float* __restrict__ atten, const float* __restrict__ rad,
    const float* __restrict__ F)
{
    const int b = blockIdx.x;
    const int t = threadIdx.x;

    if (b >= 2 * D_DIRS) {
        const int pb = b - 2 * D_DIRS;
        const float4* __restrict__ f4 =
            reinterpret_cast<const float4*>(F) + (size_t)pb * 1024;
        float4 acc = make_float4(0.f, 0.f, 0.f, 0.f);
        #pragma unroll
        for (int i = 0; i < 4; i++) {
            float4 v = f4[i * 256 + t];   // default caching -> lands in L2
            acc.x += v.x; acc.y += v.y; acc.z += v.z; acc.w += v.w;
        }
        if (t == 0) g_sink[pb] = acc.x + acc.y + acc.z + acc.w;
        return;
    }

    const bool is_b = (b >= D_DIRS);
    const int d = b & (D_DIRS - 1);
    const float* __restrict__ src = is_b ? rad : atten;
    float* __restrict__ dst = is_b ? g_bsum : g_asum;

    const float4* __restrict__ in =
        reinterpret_cast<const float4*>(src) + (size_t)d * (P_PTS * R_RANK / 4);

    float4 acc = make_float4(0.f, 0.f, 0.f, 0.f);
    #pragma unroll
    for (int i = 0; i < 16; i++) {
        float4 v = __ldcs(&in[i * 256 + t]);
        acc.x += v.x; acc.y += v.y; acc.z += v.z; acc.w += v.w;
    }

    __shared__ float4 s[256];
    s[t] = acc;
    __syncthreads();

    if (t < 16) {
        float4 sum = s[t];
        #pragma unroll
        for (int j = 1; j < 16; j++) {
            float4 v = s[j * 16 + t];
            sum.x += v.x; sum.y += v.y; sum.z += v.z; sum.w += v.w;
        }
        reinterpret_cast<float4*>(dst + d * R_RANK)[t] = sum;
    }
}

// ---------------------------------------------------------------------------
// Kernel 2: partial M over 8 d's per block. 128 blocks x 256 threads.
// ONE float4 load per thread per tensor (DRAM latency paid once, wide
// parallelism), 128 FMA/thread, plain float4 stores to g_part.
// ---------------------------------------------------------------------------
__global__ __launch_bounds__(256) void partial_m_kernel()
{
    const int b = blockIdx.x;
    const int t = threadIdx.x;

    __shared__ __align__(16) float sA[8 * R_RANK];   // 2 KB
    __shared__ __align__(16) float sB[8 * R_RANK];   // 2 KB

    const size_t base = (size_t)b * 8 * R_RANK / 4;  // float4 index
    // 8 rows x 64 floats = 128 float4 per tensor; 256 threads cover both
    if (t < 128)
        reinterpret_cast<float4*>(sA)[t] =
            reinterpret_cast<const float4*>(g_asum)[base + t];
    else
        reinterpret_cast<float4*>(sB)[t - 128] =
            reinterpret_cast<const float4*>(g_bsum)[base + (t - 128)];
    __syncthreads();

    const int r1  = t >> 2;
    const int r2b = (t & 3) * 16;

    float macc[16];
    #pragma unroll
    for (int j = 0; j < 16; j++) macc[j] = 0.f;

    #pragma unroll
    for (int i = 0; i < 8; i++) {
        const float a = sA[i * R_RANK + r1];
        #pragma unroll
        for (int j = 0; j < 16; j++)
            macc[j] += a * sB[i * R_RANK + r2b + j];
    }

    float* dst = g_part + (size_t)b * 4096 + r1 * R_RANK + r2b;
    #pragma unroll
    for (int j = 0; j < 4; j++)
        reinterpret_cast<float4*>(dst)[j] =
            make_float4(macc[4*j], macc[4*j+1], macc[4*j+2], macc[4*j+3]);
}

// ---------------------------------------------------------------------------
// Kernel 3: combine + quadform, distributed over r1.
// grid = 128 blocks = (r1 = b>>1, k-half = b&1), 256 threads.
// Block combines M row r1 from the 128 L2-hot partials, then for each of its
// 512 k's computes (Mrow . f_k) * f_k[r1] / D and atomicAdd's into out[k].
// Atomics: 32 lanes -> 32 distinct addresses (spread), depth 64 per address.
// ---------------------------------------------------------------------------
__global__ __launch_bounds__(256) void combine_quad_kernel(
    const float* __restrict__ F, float* __restrict__ out)
{
    const int t     = threadIdx.x;
    const int r1    = blockIdx.x >> 1;
    const int khalf = blockIdx.x & 1;

    __shared__ float Mrow[R_RANK];
    __shared__ float red[256];

    // ---- combine: Mrow[r2] = sum_p g_part[p][r1][r2] ----
    {
        const int r2 = t & 63;
        const int g  = t >> 6;    // 4 groups of 32 partials
        float acc = 0.f;
        const float* __restrict__ pp = g_part + (size_t)g * 32 * 4096 + r1 * R_RANK + r2;
        #pragma unroll
        for (int i = 0; i < 32; i++)
            acc += pp[(size_t)i * 4096];
        red[t] = acc;
        __syncthreads();
        if (t < 64)
            Mrow[t] = red[t] + red[64 + t] + red[128 + t] + red[192 + t];
        __syncthreads();
    }

    // ---- quadform contributions for 2 chunks of 256 k's ----
    #pragma unroll
    for (int c = 0; c < 2; c++) {
        const int k = khalf * 512 + c * 256 + t;
        const float4* __restrict__ f4 =
            reinterpret_cast<const float4*>(F) + (size_t)k * 16;

        // batched loads for MLP (L2-hot from prefetch)
        float4 v[16];
        #pragma unroll
        for (int j = 0; j < 16; j++) v[j] = f4[j];

        float dot = 0.f;
        #pragma unroll
        for (int j = 0; j < 16; j++) {
            dot += v[j].x * Mrow[4*j + 0];
            dot += v[j].y * Mrow[4*j + 1];
            dot += v[j].z * Mrow[4*j + 2];
            dot += v[j].w * Mrow[4*j + 3];
        }
        const float fr1 = F[(size_t)k * R_RANK + r1];   // L1/L2 hit (same lines)
        atomicAdd(&out[k], dot * fr1 * (1.0f / (float)D_DIRS));
    }
}

extern "C" void kernel_launch(void* const* d_in, const int* in_sizes, int n_in,
                              void* d_out, int out_size)
{
    const float* atten = (const float*)d_in[0];   // [D,P,R] fp32
    const float* rad   = (const float*)d_in[1];   // [D,P,R] fp32
    const float* F     = (const float*)d_in[2];   // [K,R]   fp32
    float* out = (float*)d_out;                   // [K]     fp32

    (void)in_sizes; (void)n_in;

    // out is an atomic accumulation target: zero it (capturable memset node)
    cudaMemsetAsync(out, 0, (size_t)out_size * sizeof(float));

    reduce_p_kernel<<<2 * D_DIRS + PREFETCH_BLOCKS, 256>>>(atten, rad, F);
    partial_m_kernel<<<NPART, 256>>>();
    combine_quad_kernel<<<2 * R_RANK, 256>>>(F, out);
}

// round 9
// speedup vs baseline: 1.3167x; 1.1011x over previous
#include <cuda_runtime.h>

// Problem shape (fixed by dataset): D=1024, P=256, R=64, K=1024
#define D_DIRS 1024
#define P_PTS  256
#define R_RANK 64
#define K_SUB  1024

#define PREFETCH_BLOCKS 16     // extra blocks in kernel 1 that warm L2 with F
#define NCHUNK 16              // d-chunks for partial M
#define CHUNK_D (D_DIRS / NCHUNK)   // 64 directions per chunk

// Scratch (allocation-free rule: __device__ globals; all fully overwritten
// every replay — no zeroing needed, no atomics anywhere)
__device__ float g_asum[D_DIRS * R_RANK];           // sum over p of attenuation
__device__ float g_bsum[D_DIRS * R_RANK];           // sum over p of radiation
__device__ float g_part[NCHUNK * R_RANK * R_RANK];  // per-chunk partial M (256 KB)
__device__ float g_sink[PREFETCH_BLOCKS];           // keeps F-prefetch alive

// ---------------------------------------------------------------------------
// Kernel 1: reduce over P. One block per (tensor, d) — 2048 short-lived,
// barrier-light blocks; proven ~24us @ 72% DRAM (the HBM roofline for this
// stream). 16 extra blocks prefetch F (256 KB) into L2 for the tail.
// Triggers programmatic launch of the dependent kernel at each block's end.
// ---------------------------------------------------------------------------
__global__ __launch_bounds__(256) void reduce_p_kernel(
    const float* __restrict__ atten, const float* __restrict__ rad,
    const float* __restrict__ F)
{
    const int b = blockIdx.x;
    const int t = threadIdx.x;

    if (b >= 2 * D_DIRS) {
        const int pb = b - 2 * D_DIRS;
        const float4* __restrict__ f4 =
            reinterpret_cast<const float4*>(F) + (size_t)pb * 1024;
        float4 acc = make_float4(0.f, 0.f, 0.f, 0.f);
        #pragma unroll
        for (int i = 0; i < 4; i++) {
            float4 v = f4[i * 256 + t];   // default caching -> lands in L2
            acc.x += v.x; acc.y += v.y; acc.z += v.z; acc.w += v.w;
        }
        if (t == 0) g_sink[pb] = acc.x + acc.y + acc.z + acc.w;
        cudaTriggerProgrammaticLaunchCompletion();
        return;
    }

    const bool is_b = (b >= D_DIRS);
    const int d = b & (D_DIRS - 1);
    const float* __restrict__ src = is_b ? rad : atten;
    float* __restrict__ dst = is_b ? g_bsum : g_asum;

    const float4* __restrict__ in =
        reinterpret_cast<const float4*>(src) + (size_t)d * (P_PTS * R_RANK / 4);

    float4 acc = make_float4(0.f, 0.f, 0.f, 0.f);
    #pragma unroll
    for (int i = 0; i < 16; i++) {
        float4 v = __ldcs(&in[i * 256 + t]);
        acc.x += v.x; acc.y += v.y; acc.z += v.z; acc.w += v.w;
    }

    __shared__ float4 s[256];
    s[t] = acc;
    __syncthreads();

    if (t < 16) {
        float4 sum = s[t];
        #pragma unroll
        for (int j = 1; j < 16; j++) {
            float4 v = s[j * 16 + t];
            sum.x += v.x; sum.y += v.y; sum.z += v.z; sum.w += v.w;
        }
        reinterpret_cast<float4*>(dst + d * R_RANK)[t] = sum;
    }
    cudaTriggerProgrammaticLaunchCompletion();
}

// ---------------------------------------------------------------------------
// Kernel 2: partial M. 64 blocks = (chunk c = b>>2 of 64 d's, r1-quarter
// q = b&3 of 16 rows) x 256 threads. Stage both 16 KB chunk slices in smem
// (8 coalesced float4 loads/thread), then each thread computes a float4 of
// the partial M tile (256 FMA) and plain-stores it. No atomics.
// ---------------------------------------------------------------------------
__global__ __launch_bounds__(256) void partial_m_kernel()
{
    __shared__ __align__(16) float sA[CHUNK_D * R_RANK];   // 16 KB
    __shared__ __align__(16) float sB[CHUNK_D * R_RANK];   // 16 KB

    const int t = threadIdx.x;
    const int c = blockIdx.x >> 2;   // d-chunk
    const int q = blockIdx.x & 3;    // r1 quarter

    cudaGridDependencySynchronize();   // wait for reduce_p's writes

    const float4* __restrict__ a4 =
        reinterpret_cast<const float4*>(g_asum) + (size_t)c * 1024;
    const float4* __restrict__ b4 =
        reinterpret_cast<const float4*>(g_bsum) + (size_t)c * 1024;
    #pragma unroll
    for (int i = 0; i < 4; i++) {
        reinterpret_cast<float4*>(sA)[i * 256 + t] = a4[i * 256 + t];
        reinterpret_cast<float4*>(sB)[i * 256 + t] = b4[i * 256 + t];
    }
    __syncthreads();

    const int r1  = q * 16 + (t >> 4);   // this block covers 16 r1 rows
    const int r2b = (t & 15) * 4;        // float4 of r2

    float4 m = make_float4(0.f, 0.f, 0.f, 0.f);
    #pragma unroll
    for (int dd = 0; dd < CHUNK_D; dd++) {
        const float a = sA[dd * R_RANK + r1];
        const float4 bv = *reinterpret_cast<const float4*>(sB + dd * R_RANK + r2b);
        m.x += a * bv.x; m.y += a * bv.y;
        m.z += a * bv.z; m.w += a * bv.w;
    }

    *reinterpret_cast<float4*>(g_part + (size_t)c * 4096 + r1 * R_RANK + r2b) = m;
    cudaTriggerProgrammaticLaunchCompletion();
}

// ---------------------------------------------------------------------------
// Kernel 3: combine + quadform. 64 blocks x 256 threads, 16 k's per block.
// Combine: thread t sums float4 slots {t, t+256, t+512, t+768} of M across
// the 16 partials — 64 fully-coalesced independent LDG.128 (L2-hot) — and
// stages M into smem. F rows staged (L2-hot from prefetch). Quadform: warp w
// handles k = w and k = w+8; lane owns an r2 float2. Plain stores to out —
// every out[k] written exactly once, no memset needed.
// ---------------------------------------------------------------------------
__global__ __launch_bounds__(256) void combine_quad_kernel(
    const float* __restrict__ F, float* __restrict__ out)
{
    __shared__ __align__(16) float Msh[R_RANK * R_RANK];   // 16 KB
    __shared__ __align__(16) float fsh[16 * R_RANK];       // 4 KB

    const int t = threadIdx.x;
    const int b = blockIdx.x;

    cudaGridDependencySynchronize();   // wait for partial_m's writes

    const float4* __restrict__ p4 = reinterpret_cast<const float4*>(g_part);
    float4 acc[4];
    #pragma unroll
    for (int i = 0; i < 4; i++) acc[i] = make_float4(0.f, 0.f, 0.f, 0.f);

    #pragma unroll
    for (int p = 0; p < NCHUNK; p++) {
        #pragma unroll
        for (int i = 0; i < 4; i++) {
            const float4 v = p4[(size_t)p * 1024 + i * 256 + t];
            acc[i].x += v.x; acc[i].y += v.y;
            acc[i].z += v.z; acc[i].w += v.w;
        }
    }
    #pragma unroll
    for (int i = 0; i < 4; i++)
        reinterpret_cast<float4*>(Msh)[i * 256 + t] = acc[i];

    // F rows for this block's 16 k's: 1024 floats = 256 float4
    reinterpret_cast<float4*>(fsh)[t] =
        reinterpret_cast<const float4*>(F)[(size_t)b * 256 + t];
    __syncthreads();

    const int w    = t >> 5;
    const int lane = t & 31;
    const float2* __restrict__ M2 = reinterpret_cast<const float2*>(Msh);

    #pragma unroll
    for (int pass = 0; pass < 2; pass++) {
        const int kl = w + pass * 8;
        const float* __restrict__ fk = fsh + kl * R_RANK;

        float2 a2 = make_float2(0.f, 0.f);
        #pragma unroll
        for (int r1 = 0; r1 < R_RANK; r1++) {
            const float fv = fk[r1];               // warp-uniform broadcast
            const float2 mv = M2[r1 * 32 + lane];
            a2.x += fv * mv.x;
            a2.y += fv * mv.y;
        }
        float val = a2.x * fk[2 * lane] + a2.y * fk[2 * lane + 1];

        #pragma unroll
        for (int off = 16; off > 0; off >>= 1)
            val += __shfl_xor_sync(0xffffffffu, val, off);

        if (lane == 0)
            out[b * 16 + kl] = val * (1.0f / (float)D_DIRS);
    }
}

extern "C" void kernel_launch(void* const* d_in, const int* in_sizes, int n_in,
                              void* d_out, int out_size)
{
    const float* atten = (const float*)d_in[0];   // [D,P,R] fp32
    const float* rad   = (const float*)d_in[1];   // [D,P,R] fp32
    const float* F     = (const float*)d_in[2];   // [K,R]   fp32
    float* out = (float*)d_out;                   // [K]     fp32

    (void)in_sizes; (void)n_in; (void)out_size;

    reduce_p_kernel<<<2 * D_DIRS + PREFETCH_BLOCKS, 256>>>(atten, rad, F);

    // PDL: dependent kernels are dispatched early and wait at
    // cudaGridDependencySynchronize, hiding the per-launch constant.
    cudaLaunchAttribute attr[1];
    attr[0].id = cudaLaunchAttributeProgrammaticStreamSerialization;
    attr[0].val.programmaticStreamSerializationAllowed = 1;

    cudaLaunchConfig_t cfg = {};
    cfg.blockDim = dim3(256, 1, 1);
    cfg.attrs = attr;
    cfg.numAttrs = 1;
    cfg.stream = 0;

    cfg.gridDim = dim3(64, 1, 1);
    cudaLaunchKernelEx(&cfg, partial_m_kernel);

    cfg.gridDim = dim3(64, 1, 1);
    cudaLaunchKernelEx(&cfg, combine_quad_kernel, F, out);
}